// round 1
// baseline (speedup 1.0000x reference)
#include <cuda_runtime.h>
#include <cuda_bf16.h>
#include <math.h>

// ---------------------------------------------------------------------------
// CrossModalFusion: q=rgb@Wq+bq; k,v=pose@W{k,v}+b; S=qk^T/sqrt(512);
// P=softmax(S); O=P@v; proj=O@Wp+bp; x=rgb+gate*proj; out=LayerNorm(x)*g+b
// B=32, Sr=Sp=2048, D=400, H=512
// ---------------------------------------------------------------------------

#define B_   32
#define SR_  2048
#define SP_  2048
#define DIM_ 400
#define HID_ 512
#define MROWS (B_ * SR_)          // 65536

// Scratch (allocation-free rule: __device__ globals)
__device__ float g_q[(size_t)MROWS * HID_];        // 128 MB
__device__ float g_k[(size_t)MROWS * HID_];        // 128 MB
__device__ float g_v[(size_t)MROWS * HID_];        // 128 MB
__device__ float g_s[(size_t)B_ * SR_ * SP_];      // 512 MB scores / attn
__device__ float g_o[(size_t)MROWS * HID_];        // 128 MB
__device__ float g_p[(size_t)MROWS * DIM_];        // 100 MB proj

// ---------------------------------------------------------------------------
// Tiled fp32 GEMM.  C[M,N] = alpha * A[M,K] @ op(B) (+ bias[n])
//   TRANS_B = false: B is [K,N] row-major
//   TRANS_B = true : B is [N,K] row-major (C = A @ B^T)
// BM=128, BN=64, BK=16, 256 threads, 8x4 per-thread microtile.
// Requires K % 16 == 0 (true for 400/512/2048). M,N edges guarded.
// ---------------------------------------------------------------------------
template <bool TRANS_B>
__global__ __launch_bounds__(256)
void gemm_kernel(const float* __restrict__ A, const float* __restrict__ Bm,
                 const float* __restrict__ bias, float* __restrict__ C,
                 int M, int N, int K,
                 long long strideA, long long strideB, long long strideC,
                 float alpha)
{
    constexpr int BM = 128, BN = 64, BK = 16;
    __shared__ float As[BK][BM + 4];   // transposed A tile, padded
    __shared__ float Bs[BK][BN + 4];   // B tile (k-major), padded

    const int bz = blockIdx.z;
    A  += (long long)bz * strideA;
    Bm += (long long)bz * strideB;
    C  += (long long)bz * strideC;

    const int m0 = blockIdx.y * BM;
    const int n0 = blockIdx.x * BN;
    const int tid = threadIdx.x;
    const int tr = tid >> 4;           // 0..15 -> rows tr*8 .. tr*8+7
    const int tc = tid & 15;           // 0..15 -> cols tc*4 .. tc*4+3

    float acc[8][4];
#pragma unroll
    for (int i = 0; i < 8; i++)
#pragma unroll
        for (int j = 0; j < 4; j++) acc[i][j] = 0.f;

    for (int k0 = 0; k0 < K; k0 += BK) {
        // ---- load A tile [BM x BK], store transposed ----
#pragma unroll
        for (int i = 0; i < 8; i++) {
            int e = tid + i * 256;           // 0..2047
            int r = e >> 4;                  // row within tile
            int c = e & 15;                  // k within tile
            int gm = m0 + r;
            float v = 0.f;
            if (gm < M) v = A[(long long)gm * K + (k0 + c)];
            As[c][r] = v;
        }
        // ---- load B tile into Bs[k][n] ----
        if (TRANS_B) {
            // Bm is [N,K]; Bs[k][n] = Bm[n0+n][k0+k]
#pragma unroll
            for (int i = 0; i < 4; i++) {
                int e = tid + i * 256;       // 0..1023
                int n = e >> 4;              // 0..63
                int c = e & 15;              // 0..15
                int gn = n0 + n;
                float v = 0.f;
                if (gn < N) v = Bm[(long long)gn * K + (k0 + c)];
                Bs[c][n] = v;
            }
        } else {
            // Bm is [K,N]; Bs[k][n] = Bm[k0+k][n0+n]
#pragma unroll
            for (int i = 0; i < 4; i++) {
                int e = tid + i * 256;
                int r = e >> 6;              // 0..15
                int n = e & 63;              // 0..63
                int gn = n0 + n;
                float v = 0.f;
                if (gn < N) v = Bm[(long long)(k0 + r) * N + gn];
                Bs[r][n] = v;
            }
        }
        __syncthreads();

        // ---- compute ----
#pragma unroll
        for (int kk = 0; kk < BK; kk++) {
            float a[8], bb[4];
            const float4 a0 = *reinterpret_cast<const float4*>(&As[kk][tr * 8]);
            const float4 a1 = *reinterpret_cast<const float4*>(&As[kk][tr * 8 + 4]);
            a[0]=a0.x; a[1]=a0.y; a[2]=a0.z; a[3]=a0.w;
            a[4]=a1.x; a[5]=a1.y; a[6]=a1.z; a[7]=a1.w;
            const float4 b0 = *reinterpret_cast<const float4*>(&Bs[kk][tc * 4]);
            bb[0]=b0.x; bb[1]=b0.y; bb[2]=b0.z; bb[3]=b0.w;
#pragma unroll
            for (int i = 0; i < 8; i++)
#pragma unroll
                for (int j = 0; j < 4; j++)
                    acc[i][j] = fmaf(a[i], bb[j], acc[i][j]);
        }
        __syncthreads();
    }

    // ---- store ----
#pragma unroll
    for (int i = 0; i < 8; i++) {
        int gm = m0 + tr * 8 + i;
        if (gm >= M) continue;
#pragma unroll
        for (int j = 0; j < 4; j++) {
            int gn = n0 + tc * 4 + j;
            if (gn < N) {
                float v = acc[i][j] * alpha;
                if (bias) v += bias[gn];
                C[(long long)gm * N + gn] = v;
            }
        }
    }
}

// ---------------------------------------------------------------------------
// Row softmax over 2048 columns, in-place. One block (256 thr) per row.
// ---------------------------------------------------------------------------
__global__ __launch_bounds__(256)
void softmax_rows_kernel(float* __restrict__ S)
{
    float* row = S + (long long)blockIdx.x * SP_;
    const int tid = threadIdx.x;
    float v[8];
    float mx = -INFINITY;
#pragma unroll
    for (int i = 0; i < 8; i++) {
        v[i] = row[tid + i * 256];
        mx = fmaxf(mx, v[i]);
    }
    __shared__ float red[256];
    red[tid] = mx;
    __syncthreads();
#pragma unroll
    for (int s = 128; s > 0; s >>= 1) {
        if (tid < s) red[tid] = fmaxf(red[tid], red[tid + s]);
        __syncthreads();
    }
    mx = red[0];
    __syncthreads();

    float sum = 0.f;
#pragma unroll
    for (int i = 0; i < 8; i++) {
        v[i] = __expf(v[i] - mx);
        sum += v[i];
    }
    red[tid] = sum;
    __syncthreads();
#pragma unroll
    for (int s = 128; s > 0; s >>= 1) {
        if (tid < s) red[tid] += red[tid + s];
        __syncthreads();
    }
    const float inv = 1.f / red[0];
#pragma unroll
    for (int i = 0; i < 8; i++)
        row[tid + i * 256] = v[i] * inv;
}

// ---------------------------------------------------------------------------
// x = rgb + gate*proj ; out = LayerNorm(x)*gamma + beta  (per row of 400)
// One block (256 thr) per row; each thread owns cols {tid, tid+256}.
// ---------------------------------------------------------------------------
__global__ __launch_bounds__(256)
void residual_ln_kernel(const float* __restrict__ proj,
                        const float* __restrict__ rgb,
                        const float* __restrict__ gamma,
                        const float* __restrict__ beta,
                        const float* __restrict__ gate,
                        float* __restrict__ out)
{
    const long long row = blockIdx.x;
    const float g = gate[0];
    const float* pr = proj + row * DIM_;
    const float* rr = rgb  + row * DIM_;
    float* orow = out + row * DIM_;
    const int tid = threadIdx.x;
    const int i1 = tid + 256;
    const bool has1 = (i1 < DIM_);

    float x0 = rr[tid] + g * pr[tid];
    float x1 = has1 ? (rr[i1] + g * pr[i1]) : 0.f;

    __shared__ float rs[256], rs2[256];
    rs[tid]  = x0 + x1;
    rs2[tid] = x0 * x0 + x1 * x1;
    __syncthreads();
#pragma unroll
    for (int s = 128; s > 0; s >>= 1) {
        if (tid < s) { rs[tid] += rs[tid + s]; rs2[tid] += rs2[tid + s]; }
        __syncthreads();
    }
    const float mean = rs[0] * (1.f / DIM_);
    const float var  = rs2[0] * (1.f / DIM_) - mean * mean;
    const float inv  = rsqrtf(var + 1e-5f);

    orow[tid] = (x0 - mean) * inv * gamma[tid] + beta[tid];
    if (has1) orow[i1] = (x1 - mean) * inv * gamma[i1] + beta[i1];
}

// ---------------------------------------------------------------------------
// Launch
// ---------------------------------------------------------------------------
extern "C" void kernel_launch(void* const* d_in, const int* in_sizes, int n_in,
                              void* d_out, int out_size)
{
    const float* rgb   = (const float*)d_in[0];
    const float* pose  = (const float*)d_in[1];
    const float* Wq    = (const float*)d_in[2];
    const float* bq    = (const float*)d_in[3];
    const float* Wk    = (const float*)d_in[4];
    const float* bk    = (const float*)d_in[5];
    const float* Wv    = (const float*)d_in[6];
    const float* bv    = (const float*)d_in[7];
    const float* Wp    = (const float*)d_in[8];
    const float* bp    = (const float*)d_in[9];
    const float* lng   = (const float*)d_in[10];
    const float* lnb   = (const float*)d_in[11];
    const float* gate  = (const float*)d_in[12];
    float* out = (float*)d_out;

    float *q, *k, *v, *s, *o, *p;
    cudaGetSymbolAddress((void**)&q, g_q);
    cudaGetSymbolAddress((void**)&k, g_k);
    cudaGetSymbolAddress((void**)&v, g_v);
    cudaGetSymbolAddress((void**)&s, g_s);
    cudaGetSymbolAddress((void**)&o, g_o);
    cudaGetSymbolAddress((void**)&p, g_p);

    const dim3 thr(256);

    // 1-3. q/k/v projections: [65536,400] @ [400,512] + bias
    {
        dim3 grid(HID_ / 64, MROWS / 128, 1);
        gemm_kernel<false><<<grid, thr>>>(rgb,  Wq, bq, q, MROWS, HID_, DIM_, 0, 0, 0, 1.f);
        gemm_kernel<false><<<grid, thr>>>(pose, Wk, bk, k, MROWS, HID_, DIM_, 0, 0, 0, 1.f);
        gemm_kernel<false><<<grid, thr>>>(pose, Wv, bv, v, MROWS, HID_, DIM_, 0, 0, 0, 1.f);
    }

    // 4. scores = q @ k^T / sqrt(512), batched over B
    {
        dim3 grid(SP_ / 64, SR_ / 128, B_);
        const float scale = 0.044194173824159216f;   // 1/sqrt(512)
        gemm_kernel<true><<<grid, thr>>>(q, k, nullptr, s,
                                         SR_, SP_, HID_,
                                         (long long)SR_ * HID_,
                                         (long long)SP_ * HID_,
                                         (long long)SR_ * SP_, scale);
    }

    // 5. softmax rows
    softmax_rows_kernel<<<B_ * SR_, thr>>>(s);

    // 6. O = attn @ v, batched
    {
        dim3 grid(HID_ / 64, SR_ / 128, B_);
        gemm_kernel<false><<<grid, thr>>>(s, v, nullptr, o,
                                          SR_, HID_, SP_,
                                          (long long)SR_ * SP_,
                                          (long long)SP_ * HID_,
                                          (long long)SR_ * HID_, 1.f);
    }

    // 7. proj = O @ Wp + bp : [65536,512] @ [512,400]
    {
        dim3 grid((DIM_ + 63) / 64, MROWS / 128, 1);
        gemm_kernel<false><<<grid, thr>>>(o, Wp, bp, p, MROWS, DIM_, HID_, 0, 0, 0, 1.f);
    }

    // 8. residual + LayerNorm
    residual_ln_kernel<<<MROWS, thr>>>(p, rgb, lng, lnb, gate, out);
}

// round 3
// speedup vs baseline: 4.2819x; 4.2819x over previous
#include <cuda_runtime.h>
#include <cuda_bf16.h>
#include <cstdint>
#include <math.h>

// ---------------------------------------------------------------------------
// CrossModalFusion via legacy tensor-core path (mma.sync tf32, sm80-style),
// portable to plain sm_103 target (no tcgen05 / no 'a' features).
// B=32, Sr=Sp=2048, D=400, H=512
// ---------------------------------------------------------------------------
#define B_   32
#define SR_  2048
#define SP_  2048
#define DIM_ 400
#define HID_ 512
#define MROWS (B_ * SR_)          // 65536

__device__ float g_q [(size_t)MROWS * HID_];
__device__ float g_k [(size_t)MROWS * HID_];
__device__ float g_vt[(size_t)MROWS * HID_];      // [B][H][Sp]
__device__ float g_s [(size_t)B_ * SR_ * SP_];
__device__ float g_o [(size_t)MROWS * HID_];
__device__ float g_p [(size_t)MROWS * DIM_];
__device__ float g_wt[4 * 512 * 400];             // WqT,WkT,WvT [512,400], WpT [400,512]

__device__ __forceinline__ uint32_t smem_u32(const void* p) {
    uint32_t a;
    asm("{ .reg .u64 t; cvta.to.shared.u64 t, %1; cvt.u32.u64 %0, t; }" : "=r"(a) : "l"(p));
    return a;
}
__device__ __forceinline__ void cp16(uint32_t dst, const void* src, int bytes) {
    asm volatile("cp.async.cg.shared.global [%0], [%1], 16, %2;"
                 :: "r"(dst), "l"(src), "r"(bytes));
}
__device__ __forceinline__ uint32_t f2tf32(uint32_t u) {
    uint32_t r;
    asm("cvt.rna.tf32.f32 %0, %1;" : "=r"(r) : "f"(__uint_as_float(u)));
    return r;
}
#define LDSM_X4(r0, r1, r2, r3, addr)                                         \
    asm volatile("ldmatrix.sync.aligned.m8n8.x4.shared.b16 {%0,%1,%2,%3}, [%4];" \
                 : "=r"(r0), "=r"(r1), "=r"(r2), "=r"(r3) : "r"(addr))

#define MMA_TF32(c, a, b0, b1)                                                \
    asm volatile("mma.sync.aligned.m16n8k8.row.col.f32.tf32.tf32.f32 "        \
                 "{%0,%1,%2,%3}, {%4,%5,%6,%7}, {%8,%9}, {%0,%1,%2,%3};"      \
                 : "+f"((c)[0]), "+f"((c)[1]), "+f"((c)[2]), "+f"((c)[3])     \
                 : "r"((a)[0]), "r"((a)[1]), "r"((a)[2]), "r"((a)[3]),        \
                   "r"(b0), "r"(b1))

// ---------------------------------------------------------------------------
// tf32 GEMM: C[M,N] = alpha * A[M,K] @ B[N,K]^T (+bias)
// CTA tile 128x128x32, 8 warps (warp tile 64x32), 3-stage cp.async,
// swizzled smem + ldmatrix (conflict-free).
// MODE 0: plain store.  MODE 1: transposed store vT[b][h][p] (b = gm>>11).
// M % 128 == 0 required. K % 4 == 0 required (rows 16B aligned).
// ---------------------------------------------------------------------------
template <int MODE>
__global__ __launch_bounds__(256)
void tf32_mma_gemm(const float* __restrict__ A, const float* __restrict__ Bm,
                   const float* __restrict__ bias, float* __restrict__ C,
                   int N, int K,
                   long long sA, long long sB, long long sC, float alpha)
{
    extern __shared__ char smem[];
    const uint32_t sb = smem_u32(smem);
    const int tid = threadIdx.x;
    const int wid = tid >> 5, lane = tid & 31;
    const int warp_m = wid & 1;        // 0..1 -> m offset 0/64
    const int warp_n = wid >> 1;       // 0..3 -> n offset 0/32/64/96

    A  += (long long)blockIdx.z * sA;
    Bm += (long long)blockIdx.z * sB;
    C  += (long long)blockIdx.z * sC;
    const int m0 = blockIdx.y * 128;
    const int n0 = blockIdx.x * 128;
    const int KT = (K + 31) >> 5;

    // Per-stage: A[128][32]f at +0 (16KB), B[128][32]f at +16KB. Swizzle:
    // addr(row, chunk16B) = row*128 + ((chunk ^ (row&7)) << 4)
    auto load_stage = [&](int kt, int s) {
        const int k0 = kt << 5;
        const uint32_t base = sb + (uint32_t)s * 32768u;
#pragma unroll
        for (int i = 0; i < 4; i++) {
            int e = tid + (i << 8);          // 0..1023
            int row = e >> 3;                // 0..127
            int c = e & 7;                   // chunk
            int kk = k0 + (c << 2);
            uint32_t off = (uint32_t)(row * 128) + (uint32_t)((c ^ (row & 7)) << 4);
            const bool kin = kk < K;
            const float* ga = A + (long long)(m0 + row) * K + kk;
            cp16(base + off, ga, kin ? 16 : 0);
            const bool bin = kin && (n0 + row) < N;
            const float* gb = Bm + (long long)(n0 + row) * K + kk;
            cp16(base + 16384u + off, bin ? gb : Bm, bin ? 16 : 0);
        }
        asm volatile("cp.async.commit_group;" ::: "memory");
    };

    float acc[4][4][4];
#pragma unroll
    for (int i = 0; i < 4; i++)
#pragma unroll
        for (int j = 0; j < 4; j++)
#pragma unroll
            for (int k = 0; k < 4; k++) acc[i][j][k] = 0.f;

    // ldmatrix lane constants
    const int t = lane >> 3, r = lane & 7;
    const uint32_t a_row = (uint32_t)(warp_m * 64 + (t & 1) * 8 + r);
    const uint32_t a_chb = (uint32_t)(t >> 1);
    const uint32_t b_row = (uint32_t)(warp_n * 32 + (t >> 1) * 8 + r);
    const uint32_t b_chb = (uint32_t)(t & 1);

    load_stage(0, 0);
    if (KT > 1) load_stage(1, 1);

    for (int kt = 0; kt < KT; kt++) {
        if (kt + 1 < KT) asm volatile("cp.async.wait_group 1;" ::: "memory");
        else             asm volatile("cp.async.wait_group 0;" ::: "memory");
        __syncthreads();
        if (kt + 2 < KT) load_stage(kt + 2, (kt + 2) % 3);

        const uint32_t baseA = sb + (uint32_t)(kt % 3) * 32768u;
        const uint32_t baseB = baseA + 16384u;

#pragma unroll
        for (int kk = 0; kk < 4; kk++) {
            uint32_t a[4][4], b[2][4];
#pragma unroll
            for (int mi = 0; mi < 4; mi++) {
                uint32_t addr = baseA + (a_row + mi * 16) * 128u
                              + ((((kk * 2) + a_chb) ^ (uint32_t)r) << 4);
                LDSM_X4(a[mi][0], a[mi][1], a[mi][2], a[mi][3], addr);
            }
#pragma unroll
            for (int j = 0; j < 2; j++) {
                uint32_t addr = baseB + (b_row + j * 16) * 128u
                              + ((((kk * 2) + b_chb) ^ (uint32_t)r) << 4);
                LDSM_X4(b[j][0], b[j][1], b[j][2], b[j][3], addr);
            }
            // round to tf32 (unbiased)
#pragma unroll
            for (int mi = 0; mi < 4; mi++)
#pragma unroll
                for (int q = 0; q < 4; q++) a[mi][q] = f2tf32(a[mi][q]);
#pragma unroll
            for (int j = 0; j < 2; j++)
#pragma unroll
                for (int q = 0; q < 4; q++) b[j][q] = f2tf32(b[j][q]);

#pragma unroll
            for (int mi = 0; mi < 4; mi++)
#pragma unroll
                for (int ni = 0; ni < 4; ni++)
                    MMA_TF32(acc[mi][ni], a[mi],
                             b[ni >> 1][(ni & 1) * 2], b[ni >> 1][(ni & 1) * 2 + 1]);
        }
    }

    // Epilogue. c0,c1: (row=lane>>2, col=2*(lane&3), +1); c2,c3: row+8.
    const int m_base = m0 + warp_m * 64;
    const int n_base = n0 + warp_n * 32;
    const int row_in = lane >> 2;
    const int col_in = (lane & 3) * 2;

#pragma unroll
    for (int mi = 0; mi < 4; mi++) {
        const int gm0 = m_base + mi * 16 + row_in;
#pragma unroll
        for (int ni = 0; ni < 4; ni++) {
            const int gn = n_base + ni * 8 + col_in;
            if (MODE == 0) {
                if (gn < N) {
                    float b0 = bias ? __ldg(&bias[gn]) : 0.f;
                    float b1 = bias ? __ldg(&bias[gn + 1]) : 0.f;
                    float2 v0 = make_float2(acc[mi][ni][0] * alpha + b0,
                                            acc[mi][ni][1] * alpha + b1);
                    float2 v1 = make_float2(acc[mi][ni][2] * alpha + b0,
                                            acc[mi][ni][3] * alpha + b1);
                    *reinterpret_cast<float2*>(&C[(long long)gm0 * N + gn]) = v0;
                    *reinterpret_cast<float2*>(&C[(long long)(gm0 + 8) * N + gn]) = v1;
                }
            } else {
                // vT[b][h][p]: b = gm>>11, p = gm&2047, h = gn ; stride_h = 2048
                long long ba0 = ((long long)(gm0 >> 11) << 20) + (gm0 & 2047);
                C[ba0 + ((long long)gn << 11)]       = acc[mi][ni][0];
                C[ba0 + ((long long)(gn + 1) << 11)] = acc[mi][ni][1];
                C[ba0 + 8 + ((long long)gn << 11)]       = acc[mi][ni][2];
                C[ba0 + 8 + ((long long)(gn + 1) << 11)] = acc[mi][ni][3];
            }
        }
    }
}

// ---------------------------------------------------------------------------
// Weight transpose: WqT/WkT/WvT [512,400]; WpT [400,512]
// ---------------------------------------------------------------------------
__global__ __launch_bounds__(256)
void transpose_w(const float* __restrict__ Wq, const float* __restrict__ Wk,
                 const float* __restrict__ Wv, const float* __restrict__ Wp,
                 float* __restrict__ out)
{
    const int SZ = 512 * 400;
    int idx = blockIdx.x * 256 + threadIdx.x;
    if (idx < 3 * SZ) {
        int w = idx / SZ, rr = idx % SZ;
        int h = rr / 400, dd = rr % 400;
        const float* W = (w == 0) ? Wq : (w == 1) ? Wk : Wv;
        out[idx] = W[dd * 512 + h];
    } else if (idx < 4 * SZ) {
        int rr = idx - 3 * SZ;
        int n = rr / 512, kk = rr % 512;
        out[idx] = Wp[kk * 400 + n];
    }
}

// ---------------------------------------------------------------------------
// Row softmax over 2048 cols, in-place
// ---------------------------------------------------------------------------
__global__ __launch_bounds__(256)
void softmax_rows_kernel(float* __restrict__ S)
{
    float* row = S + (long long)blockIdx.x * SP_;
    const int tid = threadIdx.x;
    float v[8];
    float mx = -INFINITY;
#pragma unroll
    for (int i = 0; i < 8; i++) { v[i] = row[tid + i * 256]; mx = fmaxf(mx, v[i]); }
    __shared__ float red[256];
    red[tid] = mx; __syncthreads();
#pragma unroll
    for (int s = 128; s > 0; s >>= 1) {
        if (tid < s) red[tid] = fmaxf(red[tid], red[tid + s]);
        __syncthreads();
    }
    mx = red[0]; __syncthreads();
    float sum = 0.f;
#pragma unroll
    for (int i = 0; i < 8; i++) { v[i] = __expf(v[i] - mx); sum += v[i]; }
    red[tid] = sum; __syncthreads();
#pragma unroll
    for (int s = 128; s > 0; s >>= 1) {
        if (tid < s) red[tid] += red[tid + s];
        __syncthreads();
    }
    const float inv = 1.f / red[0];
#pragma unroll
    for (int i = 0; i < 8; i++) row[tid + i * 256] = v[i] * inv;
}

// ---------------------------------------------------------------------------
// x = rgb + gate*proj ; out = LN(x)*gamma + beta
// ---------------------------------------------------------------------------
__global__ __launch_bounds__(256)
void residual_ln_kernel(const float* __restrict__ proj, const float* __restrict__ rgb,
                        const float* __restrict__ gamma, const float* __restrict__ beta,
                        const float* __restrict__ gate, float* __restrict__ out)
{
    const long long row = blockIdx.x;
    const float g = gate[0];
    const float* pr = proj + row * DIM_;
    const float* rr = rgb + row * DIM_;
    float* orow = out + row * DIM_;
    const int tid = threadIdx.x;
    const int i1 = tid + 256;
    const bool has1 = (i1 < DIM_);

    float x0 = rr[tid] + g * pr[tid];
    float x1 = has1 ? (rr[i1] + g * pr[i1]) : 0.f;

    __shared__ float rs[256], rs2[256];
    rs[tid] = x0 + x1;
    rs2[tid] = x0 * x0 + x1 * x1;
    __syncthreads();
#pragma unroll
    for (int s = 128; s > 0; s >>= 1) {
        if (tid < s) { rs[tid] += rs[tid + s]; rs2[tid] += rs2[tid + s]; }
        __syncthreads();
    }
    const float mean = rs[0] * (1.f / DIM_);
    const float var  = rs2[0] * (1.f / DIM_) - mean * mean;
    const float inv  = rsqrtf(var + 1e-5f);

    orow[tid] = (x0 - mean) * inv * gamma[tid] + beta[tid];
    if (has1) orow[i1] = (x1 - mean) * inv * gamma[i1] + beta[i1];
}

// ---------------------------------------------------------------------------
// Launch
// ---------------------------------------------------------------------------
extern "C" void kernel_launch(void* const* d_in, const int* in_sizes, int n_in,
                              void* d_out, int out_size)
{
    const float* rgb  = (const float*)d_in[0];
    const float* pose = (const float*)d_in[1];
    const float* Wq   = (const float*)d_in[2];
    const float* bq   = (const float*)d_in[3];
    const float* Wk   = (const float*)d_in[4];
    const float* bk   = (const float*)d_in[5];
    const float* Wv   = (const float*)d_in[6];
    const float* bv   = (const float*)d_in[7];
    const float* Wp   = (const float*)d_in[8];
    const float* bp   = (const float*)d_in[9];
    const float* lng  = (const float*)d_in[10];
    const float* lnb  = (const float*)d_in[11];
    const float* gate = (const float*)d_in[12];
    float* out = (float*)d_out;

    float *q, *k, *vt, *s, *o, *p, *wt;
    cudaGetSymbolAddress((void**)&q,  g_q);
    cudaGetSymbolAddress((void**)&k,  g_k);
    cudaGetSymbolAddress((void**)&vt, g_vt);
    cudaGetSymbolAddress((void**)&s,  g_s);
    cudaGetSymbolAddress((void**)&o,  g_o);
    cudaGetSymbolAddress((void**)&p,  g_p);
    cudaGetSymbolAddress((void**)&wt, g_wt);

    const int SMEM = 3 * 32768;        // 96 KB
    cudaFuncSetAttribute(tf32_mma_gemm<0>, cudaFuncAttributeMaxDynamicSharedMemorySize, SMEM);
    cudaFuncSetAttribute(tf32_mma_gemm<1>, cudaFuncAttributeMaxDynamicSharedMemorySize, SMEM);

    const int WSZ = 512 * 400;

    // 0. transpose weights
    transpose_w<<<(4 * WSZ + 255) / 256, 256>>>(Wq, Wk, Wv, Wp, wt);

    // 1-3. projections [65536,400] @ [400,512]  (B = W^T stored [512,400] K-major)
    {
        dim3 grid(4, MROWS / 128, 1);
        tf32_mma_gemm<0><<<grid, 256, SMEM>>>(rgb,  wt + 0 * WSZ, bq, q,  HID_, DIM_, 0, 0, 0, 1.f);
        tf32_mma_gemm<0><<<grid, 256, SMEM>>>(pose, wt + 1 * WSZ, bk, k,  HID_, DIM_, 0, 0, 0, 1.f);
        tf32_mma_gemm<1><<<grid, 256, SMEM>>>(pose, wt + 2 * WSZ, nullptr, vt, HID_, DIM_, 0, 0, 0, 1.f);
    }

    // 4. scores = q @ k^T / sqrt(512), batched
    {
        dim3 grid(SP_ / 128, SR_ / 128, B_);
        tf32_mma_gemm<0><<<grid, 256, SMEM>>>(q, k, nullptr, s, SP_, HID_,
                                              (long long)SR_ * HID_, (long long)SP_ * HID_,
                                              (long long)SR_ * SP_, 0.044194173824159216f);
    }

    // 5. softmax
    softmax_rows_kernel<<<B_ * SR_, 256>>>(s);

    // 6. O = attn @ v   (B = vT [H][Sp] K-major, batched)
    {
        dim3 grid(HID_ / 128, SR_ / 128, B_);
        tf32_mma_gemm<0><<<grid, 256, SMEM>>>(s, vt, nullptr, o, HID_, SP_,
                                              (long long)SR_ * SP_, (long long)HID_ * SP_,
                                              (long long)SR_ * HID_, 1.f);
    }

    // 7. proj = O @ Wp + bp   (B = WpT [400,512] K-major)
    {
        dim3 grid((DIM_ + 127) / 128, MROWS / 128, 1);
        tf32_mma_gemm<0><<<grid, 256, SMEM>>>(o, wt + 3 * WSZ, bp, p, DIM_, HID_, 0, 0, 0, 1.f);
    }

    // 8. residual + LayerNorm
    residual_ln_kernel<<<MROWS, 256>>>(p, rgb, lng, lnb, gate, out);
}

// round 5
// speedup vs baseline: 4.7597x; 1.1116x over previous
#include <cuda_runtime.h>
#include <cuda_bf16.h>
#include <cstdint>
#include <math.h>

// ---------------------------------------------------------------------------
// CrossModalFusion via legacy tensor-core path (mma.sync tf32, sm80-style).
// Round 4: operands pre-rounded to tf32 (no in-loop cvt), 2 CTAs/SM,
// coalesced vT epilogue via smem staging.
// B=32, Sr=Sp=2048, D=400, H=512
// ---------------------------------------------------------------------------
#define B_   32
#define SR_  2048
#define SP_  2048
#define DIM_ 400
#define HID_ 512
#define MROWS (B_ * SR_)          // 65536

__device__ float g_q [(size_t)MROWS * HID_];
__device__ float g_k [(size_t)MROWS * HID_];
__device__ float g_vt[(size_t)MROWS * HID_];      // [B][H][Sp]
__device__ float g_s [(size_t)B_ * SR_ * SP_];
__device__ float g_o [(size_t)MROWS * HID_];
__device__ float g_p [(size_t)MROWS * DIM_];
__device__ float g_wt[4 * 512 * 400];             // WqT,WkT,WvT [512,400], WpT [400,512]
__device__ float g_rgbt [(size_t)MROWS * DIM_];   // tf32-rounded rgb
__device__ float g_poset[(size_t)MROWS * DIM_];   // tf32-rounded pose

__device__ __forceinline__ uint32_t smem_u32(const void* p) {
    uint32_t a;
    asm("{ .reg .u64 t; cvta.to.shared.u64 t, %1; cvt.u32.u64 %0, t; }" : "=r"(a) : "l"(p));
    return a;
}
__device__ __forceinline__ void cp16(uint32_t dst, const void* src, int bytes) {
    asm volatile("cp.async.cg.shared.global [%0], [%1], 16, %2;"
                 :: "r"(dst), "l"(src), "r"(bytes));
}
__device__ __forceinline__ float rtf(float x) {
    uint32_t r;
    asm("cvt.rna.tf32.f32 %0, %1;" : "=r"(r) : "f"(x));
    return __uint_as_float(r);
}
#define LDSM_X4(r0, r1, r2, r3, addr)                                         \
    asm volatile("ldmatrix.sync.aligned.m8n8.x4.shared.b16 {%0,%1,%2,%3}, [%4];" \
                 : "=r"(r0), "=r"(r1), "=r"(r2), "=r"(r3) : "r"(addr))

#define MMA_TF32(c, a, b0, b1)                                                \
    asm volatile("mma.sync.aligned.m16n8k8.row.col.f32.tf32.tf32.f32 "        \
                 "{%0,%1,%2,%3}, {%4,%5,%6,%7}, {%8,%9}, {%0,%1,%2,%3};"      \
                 : "+f"((c)[0]), "+f"((c)[1]), "+f"((c)[2]), "+f"((c)[3])     \
                 : "r"((a)[0]), "r"((a)[1]), "r"((a)[2]), "r"((a)[3]),        \
                   "r"(b0), "r"(b1))

// ---------------------------------------------------------------------------
// tf32 GEMM: C[M,N] = alpha * A[M,K] @ B[N,K]^T (+bias)
// CTA tile 128x128x32, 8 warps (warp tile 64x32), 3-stage cp.async.
// Operands must already be tf32-rounded (no in-loop cvt).
// MODE 0: plain store.  MODE 1: transposed store vT[b][h][p] via smem.
// ROUND: round output to tf32 (for values feeding a later GEMM).
// ---------------------------------------------------------------------------
template <int MODE, int ROUND>
__global__ __launch_bounds__(256, 2)
void tf32_mma_gemm(const float* __restrict__ A, const float* __restrict__ Bm,
                   const float* __restrict__ bias, float* __restrict__ C,
                   int N, int K,
                   long long sA, long long sB, long long sC, float alpha)
{
    extern __shared__ char smem[];
    const uint32_t sb = smem_u32(smem);
    const int tid = threadIdx.x;
    const int wid = tid >> 5, lane = tid & 31;
    const int warp_m = wid & 1;
    const int warp_n = wid >> 1;

    A  += (long long)blockIdx.z * sA;
    Bm += (long long)blockIdx.z * sB;
    C  += (long long)blockIdx.z * sC;
    const int m0 = blockIdx.y * 128;
    const int n0 = blockIdx.x * 128;
    const int KT = (K + 31) >> 5;

    auto load_stage = [&](int kt, int s) {
        const int k0 = kt << 5;
        const uint32_t base = sb + (uint32_t)s * 32768u;
#pragma unroll
        for (int i = 0; i < 4; i++) {
            int e = tid + (i << 8);
            int row = e >> 3;
            int c = e & 7;
            int kk = k0 + (c << 2);
            uint32_t off = (uint32_t)(row * 128) + (uint32_t)((c ^ (row & 7)) << 4);
            const bool kin = kk < K;
            const float* ga = A + (long long)(m0 + row) * K + kk;
            cp16(base + off, ga, kin ? 16 : 0);
            const bool bin = kin && (n0 + row) < N;
            const float* gb = Bm + (long long)(n0 + row) * K + kk;
            cp16(base + 16384u + off, bin ? gb : Bm, bin ? 16 : 0);
        }
        asm volatile("cp.async.commit_group;" ::: "memory");
    };

    float acc[4][4][4];
#pragma unroll
    for (int i = 0; i < 4; i++)
#pragma unroll
        for (int j = 0; j < 4; j++)
#pragma unroll
            for (int k = 0; k < 4; k++) acc[i][j][k] = 0.f;

    const int t = lane >> 3, r = lane & 7;
    const uint32_t a_row = (uint32_t)(warp_m * 64 + (t & 1) * 8 + r);
    const uint32_t a_chb = (uint32_t)(t >> 1);
    const uint32_t b_row = (uint32_t)(warp_n * 32 + (t >> 1) * 8 + r);
    const uint32_t b_chb = (uint32_t)(t & 1);

    load_stage(0, 0);
    if (KT > 1) load_stage(1, 1);

    for (int kt = 0; kt < KT; kt++) {
        if (kt + 1 < KT) asm volatile("cp.async.wait_group 1;" ::: "memory");
        else             asm volatile("cp.async.wait_group 0;" ::: "memory");
        __syncthreads();
        if (kt + 2 < KT) load_stage(kt + 2, (kt + 2) % 3);

        const uint32_t baseA = sb + (uint32_t)(kt % 3) * 32768u;
        const uint32_t baseB = baseA + 16384u;

#pragma unroll
        for (int kk = 0; kk < 4; kk++) {
            uint32_t a[4][4], b[2][4];
#pragma unroll
            for (int mi = 0; mi < 4; mi++) {
                uint32_t addr = baseA + (a_row + mi * 16) * 128u
                              + ((((kk * 2) + a_chb) ^ (uint32_t)r) << 4);
                LDSM_X4(a[mi][0], a[mi][1], a[mi][2], a[mi][3], addr);
            }
#pragma unroll
            for (int j = 0; j < 2; j++) {
                uint32_t addr = baseB + (b_row + j * 16) * 128u
                              + ((((kk * 2) + b_chb) ^ (uint32_t)r) << 4);
                LDSM_X4(b[j][0], b[j][1], b[j][2], b[j][3], addr);
            }
#pragma unroll
            for (int mi = 0; mi < 4; mi++)
#pragma unroll
                for (int ni = 0; ni < 4; ni++)
                    MMA_TF32(acc[mi][ni], a[mi],
                             b[ni >> 1][(ni & 1) * 2], b[ni >> 1][(ni & 1) * 2 + 1]);
        }
    }

    const int m_base_l = warp_m * 64;           // local m of warp tile
    const int n_base_l = warp_n * 32;
    const int row_in = lane >> 2;
    const int col_in = (lane & 3) * 2;

    if (MODE == 0) {
#pragma unroll
        for (int mi = 0; mi < 4; mi++) {
            const int gm0 = m0 + m_base_l + mi * 16 + row_in;
#pragma unroll
            for (int ni = 0; ni < 4; ni++) {
                const int gn = n0 + n_base_l + ni * 8 + col_in;
                if (gn < N) {
                    float b0 = bias ? __ldg(&bias[gn]) : 0.f;
                    float b1 = bias ? __ldg(&bias[gn + 1]) : 0.f;
                    float v00 = acc[mi][ni][0] * alpha + b0;
                    float v01 = acc[mi][ni][1] * alpha + b1;
                    float v10 = acc[mi][ni][2] * alpha + b0;
                    float v11 = acc[mi][ni][3] * alpha + b1;
                    if (ROUND) { v00 = rtf(v00); v01 = rtf(v01); v10 = rtf(v10); v11 = rtf(v11); }
                    *reinterpret_cast<float2*>(&C[(long long)gm0 * N + gn]) = make_float2(v00, v01);
                    *reinterpret_cast<float2*>(&C[(long long)(gm0 + 8) * N + gn]) = make_float2(v10, v11);
                }
            }
        }
    } else {
        // Stage the 128x128 tile in smem as [n][m] (pad 4), write coalesced along p.
        __syncthreads();
        float* sm = reinterpret_cast<float*>(smem);
        const int PAD = 132;
#pragma unroll
        for (int mi = 0; mi < 4; mi++) {
            const int ml = m_base_l + mi * 16 + row_in;
#pragma unroll
            for (int ni = 0; ni < 4; ni++) {
                const int nl = n_base_l + ni * 8 + col_in;
                float v00 = acc[mi][ni][0], v01 = acc[mi][ni][1];
                float v10 = acc[mi][ni][2], v11 = acc[mi][ni][3];
                if (ROUND) { v00 = rtf(v00); v01 = rtf(v01); v10 = rtf(v10); v11 = rtf(v11); }
                sm[nl * PAD + ml]             = v00;
                sm[(nl + 1) * PAD + ml]       = v01;
                sm[nl * PAD + ml + 8]         = v10;
                sm[(nl + 1) * PAD + ml + 8]   = v11;
            }
        }
        __syncthreads();
        // vT[b][h][p]: b = m0>>11, p-base = m0&2047
        const long long obase = ((long long)(m0 >> 11) << 20) + (m0 & 2047);
        const int nrow = tid >> 5;          // 0..7
        const int m4 = (tid & 31) << 2;     // 0..124
#pragma unroll
        for (int pass = 0; pass < 16; pass++) {
            int n = pass * 8 + nrow;
            float4 v = *reinterpret_cast<float4*>(&sm[n * PAD + m4]);
            *reinterpret_cast<float4*>(&C[obase + ((long long)(n0 + n) << 11) + m4]) = v;
        }
    }
}

// ---------------------------------------------------------------------------
// Pre-round rgb & pose to tf32 copies
// ---------------------------------------------------------------------------
__global__ __launch_bounds__(256)
void prep_round(const float* __restrict__ rgb, const float* __restrict__ pose,
                float* __restrict__ rgbt, float* __restrict__ poset)
{
    const long long NEL4 = (long long)MROWS * DIM_ / 4;   // per tensor, float4
    long long idx = (long long)blockIdx.x * 256 + threadIdx.x;
    if (idx < NEL4) {
        float4 v = reinterpret_cast<const float4*>(rgb)[idx];
        v.x = rtf(v.x); v.y = rtf(v.y); v.z = rtf(v.z); v.w = rtf(v.w);
        reinterpret_cast<float4*>(rgbt)[idx] = v;
    } else if (idx < 2 * NEL4) {
        long long j = idx - NEL4;
        float4 v = reinterpret_cast<const float4*>(pose)[j];
        v.x = rtf(v.x); v.y = rtf(v.y); v.z = rtf(v.z); v.w = rtf(v.w);
        reinterpret_cast<float4*>(poset)[j] = v;
    }
}

// ---------------------------------------------------------------------------
// Weight transpose (+tf32 round): WqT/WkT/WvT [512,400]; WpT [400,512]
// ---------------------------------------------------------------------------
__global__ __launch_bounds__(256)
void transpose_w(const float* __restrict__ Wq, const float* __restrict__ Wk,
                 const float* __restrict__ Wv, const float* __restrict__ Wp,
                 float* __restrict__ out)
{
    const int SZ = 512 * 400;
    int idx = blockIdx.x * 256 + threadIdx.x;
    if (idx < 3 * SZ) {
        int w = idx / SZ, rr = idx % SZ;
        int h = rr / 400, dd = rr % 400;
        const float* W = (w == 0) ? Wq : (w == 1) ? Wk : Wv;
        out[idx] = rtf(W[dd * 512 + h]);
    } else if (idx < 4 * SZ) {
        int rr = idx - 3 * SZ;
        int n = rr / 512, kk = rr % 512;
        out[idx] = rtf(Wp[kk * 400 + n]);
    }
}

// ---------------------------------------------------------------------------
// Row softmax over 2048 cols, in-place, output rounded to tf32
// ---------------------------------------------------------------------------
__global__ __launch_bounds__(256)
void softmax_rows_kernel(float* __restrict__ S)
{
    float4* row = reinterpret_cast<float4*>(S + (long long)blockIdx.x * SP_);
    const int tid = threadIdx.x;
    float4 v[2];
    float mx = -INFINITY;
#pragma unroll
    for (int i = 0; i < 2; i++) {
        v[i] = row[tid + i * 256];
        mx = fmaxf(mx, fmaxf(fmaxf(v[i].x, v[i].y), fmaxf(v[i].z, v[i].w)));
    }
    __shared__ float red[256];
    red[tid] = mx; __syncthreads();
#pragma unroll
    for (int s = 128; s > 0; s >>= 1) {
        if (tid < s) red[tid] = fmaxf(red[tid], red[tid + s]);
        __syncthreads();
    }
    mx = red[0]; __syncthreads();
    float sum = 0.f;
#pragma unroll
    for (int i = 0; i < 2; i++) {
        v[i].x = __expf(v[i].x - mx); v[i].y = __expf(v[i].y - mx);
        v[i].z = __expf(v[i].z - mx); v[i].w = __expf(v[i].w - mx);
        sum += v[i].x + v[i].y + v[i].z + v[i].w;
    }
    red[tid] = sum; __syncthreads();
#pragma unroll
    for (int s = 128; s > 0; s >>= 1) {
        if (tid < s) red[tid] += red[tid + s];
        __syncthreads();
    }
    const float inv = 1.f / red[0];
#pragma unroll
    for (int i = 0; i < 2; i++) {
        v[i].x = rtf(v[i].x * inv); v[i].y = rtf(v[i].y * inv);
        v[i].z = rtf(v[i].z * inv); v[i].w = rtf(v[i].w * inv);
        row[tid + i * 256] = v[i];
    }
}

// ---------------------------------------------------------------------------
// x = rgb + gate*proj ; out = LN(x)*gamma + beta
// ---------------------------------------------------------------------------
__global__ __launch_bounds__(256)
void residual_ln_kernel(const float* __restrict__ proj, const float* __restrict__ rgb,
                        const float* __restrict__ gamma, const float* __restrict__ beta,
                        const float* __restrict__ gate, float* __restrict__ out)
{
    const long long row = blockIdx.x;
    const float g = gate[0];
    const float* pr = proj + row * DIM_;
    const float* rr = rgb + row * DIM_;
    float* orow = out + row * DIM_;
    const int tid = threadIdx.x;
    const int i1 = tid + 256;
    const bool has1 = (i1 < DIM_);

    float x0 = rr[tid] + g * pr[tid];
    float x1 = has1 ? (rr[i1] + g * pr[i1]) : 0.f;

    __shared__ float rs[256], rs2[256];
    rs[tid] = x0 + x1;
    rs2[tid] = x0 * x0 + x1 * x1;
    __syncthreads();
#pragma unroll
    for (int s = 128; s > 0; s >>= 1) {
        if (tid < s) { rs[tid] += rs[tid + s]; rs2[tid] += rs2[tid + s]; }
        __syncthreads();
    }
    const float mean = rs[0] * (1.f / DIM_);
    const float var  = rs2[0] * (1.f / DIM_) - mean * mean;
    const float inv  = rsqrtf(var + 1e-5f);

    orow[tid] = (x0 - mean) * inv * gamma[tid] + beta[tid];
    if (has1) orow[i1] = (x1 - mean) * inv * gamma[i1] + beta[i1];
}

// ---------------------------------------------------------------------------
// Launch
// ---------------------------------------------------------------------------
extern "C" void kernel_launch(void* const* d_in, const int* in_sizes, int n_in,
                              void* d_out, int out_size)
{
    const float* rgb  = (const float*)d_in[0];
    const float* pose = (const float*)d_in[1];
    const float* Wq   = (const float*)d_in[2];
    const float* bq   = (const float*)d_in[3];
    const float* Wk   = (const float*)d_in[4];
    const float* bk   = (const float*)d_in[5];
    const float* Wv   = (const float*)d_in[6];
    const float* bv   = (const float*)d_in[7];
    const float* Wp   = (const float*)d_in[8];
    const float* bp   = (const float*)d_in[9];
    const float* lng  = (const float*)d_in[10];
    const float* lnb  = (const float*)d_in[11];
    const float* gate = (const float*)d_in[12];
    float* out = (float*)d_out;

    float *q, *k, *vt, *s, *o, *p, *wt, *rgbt, *poset;
    cudaGetSymbolAddress((void**)&q,  g_q);
    cudaGetSymbolAddress((void**)&k,  g_k);
    cudaGetSymbolAddress((void**)&vt, g_vt);
    cudaGetSymbolAddress((void**)&s,  g_s);
    cudaGetSymbolAddress((void**)&o,  g_o);
    cudaGetSymbolAddress((void**)&p,  g_p);
    cudaGetSymbolAddress((void**)&wt, g_wt);
    cudaGetSymbolAddress((void**)&rgbt,  g_rgbt);
    cudaGetSymbolAddress((void**)&poset, g_poset);

    const int SMEM = 3 * 32768;        // 96 KB (also covers 67.6KB epilogue tile)
    cudaFuncSetAttribute(tf32_mma_gemm<0,0>, cudaFuncAttributeMaxDynamicSharedMemorySize, SMEM);
    cudaFuncSetAttribute(tf32_mma_gemm<0,1>, cudaFuncAttributeMaxDynamicSharedMemorySize, SMEM);
    cudaFuncSetAttribute(tf32_mma_gemm<1,1>, cudaFuncAttributeMaxDynamicSharedMemorySize, SMEM);

    const int WSZ = 512 * 400;

    // 0. prep: round inputs + transpose/round weights
    {
        long long n4 = 2LL * MROWS * DIM_ / 4;
        prep_round<<<(unsigned)((n4 + 255) / 256), 256>>>(rgb, pose, rgbt, poset);
        transpose_w<<<(4 * WSZ + 255) / 256, 256>>>(Wq, Wk, Wv, Wp, wt);
    }

    // 1-3. projections [65536,400] @ [400,512]
    {
        dim3 grid(4, MROWS / 128, 1);
        tf32_mma_gemm<0,1><<<grid, 256, SMEM>>>(rgbt,  wt + 0 * WSZ, bq, q,  HID_, DIM_, 0, 0, 0, 1.f);
        tf32_mma_gemm<0,1><<<grid, 256, SMEM>>>(poset, wt + 1 * WSZ, bk, k,  HID_, DIM_, 0, 0, 0, 1.f);
        tf32_mma_gemm<1,1><<<grid, 256, SMEM>>>(poset, wt + 2 * WSZ, nullptr, vt, HID_, DIM_, 0, 0, 0, 1.f);
    }

    // 4. scores = q @ k^T / sqrt(512), batched
    {
        dim3 grid(SP_ / 128, SR_ / 128, B_);
        tf32_mma_gemm<0,0><<<grid, 256, SMEM>>>(q, k, nullptr, s, SP_, HID_,
                                                (long long)SR_ * HID_, (long long)SP_ * HID_,
                                                (long long)SR_ * SP_, 0.044194173824159216f);
    }

    // 5. softmax (rounds output)
    softmax_rows_kernel<<<B_ * SR_, 256>>>(s);

    // 6. O = attn @ v   (B = vT [H][Sp] K-major, batched)
    {
        dim3 grid(HID_ / 128, SR_ / 128, B_);
        tf32_mma_gemm<0,1><<<grid, 256, SMEM>>>(s, vt, nullptr, o, HID_, SP_,
                                                (long long)SR_ * SP_, (long long)HID_ * SP_,
                                                (long long)SR_ * HID_, 1.f);
    }

    // 7. proj = O @ Wp + bp  (exact store)
    {
        dim3 grid((DIM_ + 127) / 128, MROWS / 128, 1);
        tf32_mma_gemm<0,0><<<grid, 256, SMEM>>>(o, wt + 3 * WSZ, bp, p, DIM_, HID_, 0, 0, 0, 1.f);
    }

    // 8. residual + LayerNorm
    residual_ln_kernel<<<MROWS, 256>>>(p, rgb, lng, lnb, gate, out);
}

// round 6
// speedup vs baseline: 7.1289x; 1.4977x over previous
#include <cuda_runtime.h>
#include <cuda_fp16.h>
#include <cstdint>
#include <math.h>

// ---------------------------------------------------------------------------
// CrossModalFusion via legacy fp16 tensor path (mma.sync m16n8k16, f32 acc).
// B=32, Sr=Sp=2048, D=400, H=512
// ---------------------------------------------------------------------------
#define B_   32
#define SR_  2048
#define SP_  2048
#define DIM_ 400
#define HID_ 512
#define MROWS (B_ * SR_)          // 65536

__device__ __half g_q [(size_t)MROWS * HID_];     // 64 MB
__device__ __half g_k [(size_t)MROWS * HID_];
__device__ __half g_vt[(size_t)MROWS * HID_];     // [B][H][Sp]
__device__ float  g_s [(size_t)B_ * SR_ * SP_];   // 512 MB scores (fp32)
__device__ __half g_ph[(size_t)B_ * SR_ * SP_];   // 256 MB probs (half)
__device__ __half g_o [(size_t)MROWS * HID_];
__device__ float  g_p [(size_t)MROWS * DIM_];     // 100 MB
__device__ __half g_wt[4 * 512 * 400];            // WqT,WkT,WvT [512,400], WpT [400,512]
__device__ __half g_rgbh [(size_t)MROWS * DIM_];  // 50 MB
__device__ __half g_poseh[(size_t)MROWS * DIM_];

__device__ __forceinline__ uint32_t smem_u32(const void* p) {
    uint32_t a;
    asm("{ .reg .u64 t; cvta.to.shared.u64 t, %1; cvt.u32.u64 %0, t; }" : "=r"(a) : "l"(p));
    return a;
}
__device__ __forceinline__ void cp16(uint32_t dst, const void* src, int bytes) {
    asm volatile("cp.async.cg.shared.global [%0], [%1], 16, %2;"
                 :: "r"(dst), "l"(src), "r"(bytes));
}
#define LDSM_X4(r0, r1, r2, r3, addr)                                         \
    asm volatile("ldmatrix.sync.aligned.m8n8.x4.shared.b16 {%0,%1,%2,%3}, [%4];" \
                 : "=r"(r0), "=r"(r1), "=r"(r2), "=r"(r3) : "r"(addr))

#define MMA_F16(c, a0, a1, a2, a3, b0, b1)                                    \
    asm volatile("mma.sync.aligned.m16n8k16.row.col.f32.f16.f16.f32 "         \
                 "{%0,%1,%2,%3}, {%4,%5,%6,%7}, {%8,%9}, {%0,%1,%2,%3};"      \
                 : "+f"((c)[0]), "+f"((c)[1]), "+f"((c)[2]), "+f"((c)[3])     \
                 : "r"(a0), "r"(a1), "r"(a2), "r"(a3), "r"(b0), "r"(b1))

// ---------------------------------------------------------------------------
// fp16 GEMM: C[M,N] = alpha * A[M,K] @ B[N,K]^T (+bias), f32 accumulate.
// A,B half, K-major. CTA tile 128x128, BK=64 halves (128B rows), 3 stages.
// 8 warps, warp tile 64x32.
// MODE 0: plain store (OUT_HALF picks half2/float2).
// MODE 1: transposed store vT[b][h][p] via smem staging (half out).
// ---------------------------------------------------------------------------
template <int MODE, int OUT_HALF>
__global__ __launch_bounds__(256, 2)
void h16_mma_gemm(const __half* __restrict__ A, const __half* __restrict__ Bm,
                  const float* __restrict__ bias, void* __restrict__ Cv,
                  int N, int K,
                  long long sA, long long sB, long long sC, float alpha)
{
    extern __shared__ char smem[];
    const uint32_t sb = smem_u32(smem);
    const int tid = threadIdx.x;
    const int wid = tid >> 5, lane = tid & 31;
    const int warp_m = wid & 1;        // m offset 0/64
    const int warp_n = wid >> 1;       // n offset 0/32/64/96

    A  += (long long)blockIdx.z * sA;
    Bm += (long long)blockIdx.z * sB;
    const int m0 = blockIdx.y * 128;
    const int n0 = blockIdx.x * 128;
    const int KT = (K + 63) >> 6;

    // Stage: A [128][64]h (16KB, 128B rows, 8 chunks) + B same at +16KB.
    // swizzle: chunk' = chunk ^ (row & 7)
    auto load_stage = [&](int kt, int s) {
        const int k0 = kt << 6;
        const uint32_t base = sb + (uint32_t)s * 32768u;
#pragma unroll
        for (int i = 0; i < 4; i++) {
            int e = tid + (i << 8);          // 0..1023
            int row = e >> 3;                // 0..127
            int c = e & 7;                   // chunk (8 halves)
            int kk = k0 + (c << 3);
            uint32_t off = (uint32_t)(row * 128) + (uint32_t)((c ^ (row & 7)) << 4);
            const bool kin = kk < K;
            const __half* ga = A + (long long)(m0 + row) * K + kk;
            cp16(base + off, ga, kin ? 16 : 0);
            const bool bin = kin && (n0 + row) < N;
            const __half* gb = Bm + (long long)(n0 + row) * K + kk;
            cp16(base + 16384u + off, bin ? gb : Bm, bin ? 16 : 0);
        }
        asm volatile("cp.async.commit_group;" ::: "memory");
    };

    float acc[4][4][4];
#pragma unroll
    for (int i = 0; i < 4; i++)
#pragma unroll
        for (int j = 0; j < 4; j++)
#pragma unroll
            for (int k = 0; k < 4; k++) acc[i][j][k] = 0.f;

    // ldmatrix lane mapping (x4 over 16x16-half region; tiles ordered
    // [r0..7,c0],[r8..15,c0],[r0..7,c1],[r8..15,c1] = mma a0..a3 / (b0,b1) pairs)
    const int t = lane >> 3, r = lane & 7;
    const uint32_t a_row = (uint32_t)(warp_m * 64 + (t & 1) * 8 + r);
    const uint32_t b_row = (uint32_t)(warp_n * 32 + (t & 1) * 8 + r);
    const uint32_t chb   = (uint32_t)(t >> 1);

    load_stage(0, 0);
    if (KT > 1) load_stage(1, 1);

    for (int kt = 0; kt < KT; kt++) {
        if (kt + 1 < KT) asm volatile("cp.async.wait_group 1;" ::: "memory");
        else             asm volatile("cp.async.wait_group 0;" ::: "memory");
        __syncthreads();
        if (kt + 2 < KT) load_stage(kt + 2, (kt + 2) % 3);

        const uint32_t baseA = sb + (uint32_t)(kt % 3) * 32768u;
        const uint32_t baseB = baseA + 16384u;

#pragma unroll
        for (int ks = 0; ks < 4; ks++) {      // k16 steps inside BK=64
            uint32_t a[4][4], b[2][4];
#pragma unroll
            for (int mi = 0; mi < 4; mi++) {
                uint32_t addr = baseA + (a_row + mi * 16) * 128u
                              + ((((ks * 2) + chb) ^ (uint32_t)r) << 4);
                LDSM_X4(a[mi][0], a[mi][1], a[mi][2], a[mi][3], addr);
            }
#pragma unroll
            for (int j = 0; j < 2; j++) {
                uint32_t addr = baseB + (b_row + j * 16) * 128u
                              + ((((ks * 2) + chb) ^ (uint32_t)r) << 4);
                LDSM_X4(b[j][0], b[j][1], b[j][2], b[j][3], addr);
            }
            // b tile j covers n16: frag n0-7 = (r0, r2), n8-15 = (r1, r3)
#pragma unroll
            for (int mi = 0; mi < 4; mi++)
#pragma unroll
                for (int ni = 0; ni < 4; ni++)
                    MMA_F16(acc[mi][ni], a[mi][0], a[mi][1], a[mi][2], a[mi][3],
                            b[ni >> 1][ni & 1], b[ni >> 1][(ni & 1) + 2]);
        }
    }

    const int m_base_l = warp_m * 64;
    const int n_base_l = warp_n * 32;
    const int row_in = lane >> 2;
    const int col_in = (lane & 3) * 2;

    if (MODE == 0) {
#pragma unroll
        for (int mi = 0; mi < 4; mi++) {
            const int gm0 = m0 + m_base_l + mi * 16 + row_in;
#pragma unroll
            for (int ni = 0; ni < 4; ni++) {
                const int gn = n0 + n_base_l + ni * 8 + col_in;
                if (gn < N) {
                    float b0 = bias ? __ldg(&bias[gn]) : 0.f;
                    float b1 = bias ? __ldg(&bias[gn + 1]) : 0.f;
                    float v00 = acc[mi][ni][0] * alpha + b0;
                    float v01 = acc[mi][ni][1] * alpha + b1;
                    float v10 = acc[mi][ni][2] * alpha + b0;
                    float v11 = acc[mi][ni][3] * alpha + b1;
                    if (OUT_HALF) {
                        __half* C = (__half*)Cv + (long long)blockIdx.z * sC;
                        *reinterpret_cast<__half2*>(&C[(long long)gm0 * N + gn]) =
                            __floats2half2_rn(v00, v01);
                        *reinterpret_cast<__half2*>(&C[(long long)(gm0 + 8) * N + gn]) =
                            __floats2half2_rn(v10, v11);
                    } else {
                        float* C = (float*)Cv + (long long)blockIdx.z * sC;
                        *reinterpret_cast<float2*>(&C[(long long)gm0 * N + gn]) =
                            make_float2(v00, v01);
                        *reinterpret_cast<float2*>(&C[(long long)(gm0 + 8) * N + gn]) =
                            make_float2(v10, v11);
                    }
                }
            }
        }
    } else {
        // vT: stage [n][m] half tile in smem (PAD=136 halves -> 272B rows, 16B mult)
        __syncthreads();
        __half* sm = reinterpret_cast<__half*>(smem);
        const int PAD = 136;
#pragma unroll
        for (int mi = 0; mi < 4; mi++) {
            const int ml = m_base_l + mi * 16 + row_in;
#pragma unroll
            for (int ni = 0; ni < 4; ni++) {
                const int nl = n_base_l + ni * 8 + col_in;
                sm[nl * PAD + ml]           = __float2half_rn(acc[mi][ni][0]);
                sm[(nl + 1) * PAD + ml]     = __float2half_rn(acc[mi][ni][1]);
                sm[nl * PAD + ml + 8]       = __float2half_rn(acc[mi][ni][2]);
                sm[(nl + 1) * PAD + ml + 8] = __float2half_rn(acc[mi][ni][3]);
            }
        }
        __syncthreads();
        __half* C = (__half*)Cv;   // vT base
        const long long obase = ((long long)(m0 >> 11) << 20) + (m0 & 2047);
#pragma unroll
        for (int pass = 0; pass < 8; pass++) {
            int chunk = pass * 256 + tid;       // 2048 chunks of 8 halves
            int n = chunk >> 4;
            int mc = (chunk & 15) << 3;
            uint4 v = *reinterpret_cast<uint4*>(&sm[n * PAD + mc]);
            *reinterpret_cast<uint4*>(&C[obase + ((long long)(n0 + n) << 11) + mc]) = v;
        }
    }
}

// ---------------------------------------------------------------------------
// rgb & pose -> half copies
// ---------------------------------------------------------------------------
__global__ __launch_bounds__(256)
void prep_half(const float* __restrict__ rgb, const float* __restrict__ pose,
               __half* __restrict__ rgbh, __half* __restrict__ poseh)
{
    const long long NEL4 = (long long)MROWS * DIM_ / 4;
    long long idx = (long long)blockIdx.x * 256 + threadIdx.x;
    const float* src; __half* dst; long long j;
    if (idx < NEL4)            { src = rgb;  dst = rgbh;  j = idx; }
    else if (idx < 2 * NEL4)   { src = pose; dst = poseh; j = idx - NEL4; }
    else return;
    float4 v = reinterpret_cast<const float4*>(src)[j];
    __half2 h0 = __floats2half2_rn(v.x, v.y);
    __half2 h1 = __floats2half2_rn(v.z, v.w);
    reinterpret_cast<uint2*>(dst)[j] = make_uint2(
        *reinterpret_cast<uint32_t*>(&h0), *reinterpret_cast<uint32_t*>(&h1));
}

// ---------------------------------------------------------------------------
// Weight transpose -> half: WqT/WkT/WvT [512,400]; WpT [400,512]
// ---------------------------------------------------------------------------
__global__ __launch_bounds__(256)
void transpose_w(const float* __restrict__ Wq, const float* __restrict__ Wk,
                 const float* __restrict__ Wv, const float* __restrict__ Wp,
                 __half* __restrict__ out)
{
    const int SZ = 512 * 400;
    int idx = blockIdx.x * 256 + threadIdx.x;
    if (idx < 3 * SZ) {
        int w = idx / SZ, rr = idx % SZ;
        int h = rr / 400, dd = rr % 400;
        const float* W = (w == 0) ? Wq : (w == 1) ? Wk : Wv;
        out[idx] = __float2half_rn(W[dd * 512 + h]);
    } else if (idx < 4 * SZ) {
        int rr = idx - 3 * SZ;
        int n = rr / 512, kk = rr % 512;
        out[idx] = __float2half_rn(Wp[kk * 400 + n]);
    }
}

// ---------------------------------------------------------------------------
// Row softmax over 2048 fp32 scores -> half probs
// ---------------------------------------------------------------------------
__global__ __launch_bounds__(256)
void softmax_rows_kernel(const float* __restrict__ S, __half* __restrict__ P)
{
    const float4* row = reinterpret_cast<const float4*>(S + (long long)blockIdx.x * SP_);
    uint2* prow = reinterpret_cast<uint2*>(P + (long long)blockIdx.x * SP_);
    const int tid = threadIdx.x;
    float4 v[2];
    float mx = -INFINITY;
#pragma unroll
    for (int i = 0; i < 2; i++) {
        v[i] = row[tid + i * 256];
        mx = fmaxf(mx, fmaxf(fmaxf(v[i].x, v[i].y), fmaxf(v[i].z, v[i].w)));
    }
    __shared__ float red[256];
    red[tid] = mx; __syncthreads();
#pragma unroll
    for (int s = 128; s > 0; s >>= 1) {
        if (tid < s) red[tid] = fmaxf(red[tid], red[tid + s]);
        __syncthreads();
    }
    mx = red[0]; __syncthreads();
    float sum = 0.f;
#pragma unroll
    for (int i = 0; i < 2; i++) {
        v[i].x = __expf(v[i].x - mx); v[i].y = __expf(v[i].y - mx);
        v[i].z = __expf(v[i].z - mx); v[i].w = __expf(v[i].w - mx);
        sum += v[i].x + v[i].y + v[i].z + v[i].w;
    }
    red[tid] = sum; __syncthreads();
#pragma unroll
    for (int s = 128; s > 0; s >>= 1) {
        if (tid < s) red[tid] += red[tid + s];
        __syncthreads();
    }
    const float inv = 1.f / red[0];
#pragma unroll
    for (int i = 0; i < 2; i++) {
        __half2 h0 = __floats2half2_rn(v[i].x * inv, v[i].y * inv);
        __half2 h1 = __floats2half2_rn(v[i].z * inv, v[i].w * inv);
        prow[tid + i * 256] = make_uint2(
            *reinterpret_cast<uint32_t*>(&h0), *reinterpret_cast<uint32_t*>(&h1));
    }
}

// ---------------------------------------------------------------------------
// x = rgb + gate*proj ; out = LN(x)*gamma + beta
// ---------------------------------------------------------------------------
__global__ __launch_bounds__(256)
void residual_ln_kernel(const float* __restrict__ proj, const float* __restrict__ rgb,
                        const float* __restrict__ gamma, const float* __restrict__ beta,
                        const float* __restrict__ gate, float* __restrict__ out)
{
    const long long row = blockIdx.x;
    const float g = gate[0];
    const float* pr = proj + row * DIM_;
    const float* rr = rgb + row * DIM_;
    float* orow = out + row * DIM_;
    const int tid = threadIdx.x;
    const int i1 = tid + 256;
    const bool has1 = (i1 < DIM_);

    float x0 = rr[tid] + g * pr[tid];
    float x1 = has1 ? (rr[i1] + g * pr[i1]) : 0.f;

    __shared__ float rs[256], rs2[256];
    rs[tid] = x0 + x1;
    rs2[tid] = x0 * x0 + x1 * x1;
    __syncthreads();
#pragma unroll
    for (int s = 128; s > 0; s >>= 1) {
        if (tid < s) { rs[tid] += rs[tid + s]; rs2[tid] += rs2[tid + s]; }
        __syncthreads();
    }
    const float mean = rs[0] * (1.f / DIM_);
    const float var  = rs2[0] * (1.f / DIM_) - mean * mean;
    const float inv  = rsqrtf(var + 1e-5f);

    orow[tid] = (x0 - mean) * inv * gamma[tid] + beta[tid];
    if (has1) orow[i1] = (x1 - mean) * inv * gamma[i1] + beta[i1];
}

// ---------------------------------------------------------------------------
// Launch
// ---------------------------------------------------------------------------
extern "C" void kernel_launch(void* const* d_in, const int* in_sizes, int n_in,
                              void* d_out, int out_size)
{
    const float* rgb  = (const float*)d_in[0];
    const float* pose = (const float*)d_in[1];
    const float* Wq   = (const float*)d_in[2];
    const float* bq   = (const float*)d_in[3];
    const float* Wk   = (const float*)d_in[4];
    const float* bk   = (const float*)d_in[5];
    const float* Wv   = (const float*)d_in[6];
    const float* bv   = (const float*)d_in[7];
    const float* Wp   = (const float*)d_in[8];
    const float* bp   = (const float*)d_in[9];
    const float* lng  = (const float*)d_in[10];
    const float* lnb  = (const float*)d_in[11];
    const float* gate = (const float*)d_in[12];
    float* out = (float*)d_out;

    __half *q, *k, *vt, *ph, *o, *wt, *rgbh, *poseh;
    float *s, *p;
    cudaGetSymbolAddress((void**)&q,  g_q);
    cudaGetSymbolAddress((void**)&k,  g_k);
    cudaGetSymbolAddress((void**)&vt, g_vt);
    cudaGetSymbolAddress((void**)&s,  g_s);
    cudaGetSymbolAddress((void**)&ph, g_ph);
    cudaGetSymbolAddress((void**)&o,  g_o);
    cudaGetSymbolAddress((void**)&p,  g_p);
    cudaGetSymbolAddress((void**)&wt, g_wt);
    cudaGetSymbolAddress((void**)&rgbh,  g_rgbh);
    cudaGetSymbolAddress((void**)&poseh, g_poseh);

    const int SMEM = 3 * 32768;        // 96 KB
    cudaFuncSetAttribute(h16_mma_gemm<0,0>, cudaFuncAttributeMaxDynamicSharedMemorySize, SMEM);
    cudaFuncSetAttribute(h16_mma_gemm<0,1>, cudaFuncAttributeMaxDynamicSharedMemorySize, SMEM);
    cudaFuncSetAttribute(h16_mma_gemm<1,1>, cudaFuncAttributeMaxDynamicSharedMemorySize, SMEM);

    const int WSZ = 512 * 400;

    // 0. prep
    {
        long long n4 = 2LL * MROWS * DIM_ / 4;
        prep_half<<<(unsigned)((n4 + 255) / 256), 256>>>(rgb, pose, rgbh, poseh);
        transpose_w<<<(4 * WSZ + 255) / 256, 256>>>(Wq, Wk, Wv, Wp, wt);
    }

    // 1-3. projections [65536,400] @ [400,512] -> half
    {
        dim3 grid(4, MROWS / 128, 1);
        h16_mma_gemm<0,1><<<grid, 256, SMEM>>>(rgbh,  wt + 0 * WSZ, bq, q,  HID_, DIM_, 0, 0, 0, 1.f);
        h16_mma_gemm<0,1><<<grid, 256, SMEM>>>(poseh, wt + 1 * WSZ, bk, k,  HID_, DIM_, 0, 0, 0, 1.f);
        h16_mma_gemm<1,1><<<grid, 256, SMEM>>>(poseh, wt + 2 * WSZ, nullptr, vt, HID_, DIM_, 0, 0, 0, 1.f);
    }

    // 4. scores = q @ k^T / sqrt(512) -> fp32, batched
    {
        dim3 grid(SP_ / 128, SR_ / 128, B_);
        h16_mma_gemm<0,0><<<grid, 256, SMEM>>>(q, k, nullptr, s, SP_, HID_,
                                               (long long)SR_ * HID_, (long long)SP_ * HID_,
                                               (long long)SR_ * SP_, 0.044194173824159216f);
    }

    // 5. softmax fp32 -> half probs
    softmax_rows_kernel<<<B_ * SR_, 256>>>(s, ph);

    // 6. O = probs @ v (B = vT [H][Sp] K-major), -> half, batched
    {
        dim3 grid(HID_ / 128, SR_ / 128, B_);
        h16_mma_gemm<0,1><<<grid, 256, SMEM>>>(ph, vt, nullptr, o, HID_, SP_,
                                               (long long)SR_ * SP_, (long long)HID_ * SP_,
                                               (long long)SR_ * HID_, 1.f);
    }

    // 7. proj = O @ Wp + bp -> fp32
    {
        dim3 grid((DIM_ + 127) / 128, MROWS / 128, 1);
        h16_mma_gemm<0,0><<<grid, 256, SMEM>>>(o, wt + 3 * WSZ, bp, p, DIM_, HID_, 0, 0, 0, 1.f);
    }

    // 8. residual + LayerNorm
    residual_ln_kernel<<<MROWS, 256>>>(p, rgb, lng, lnb, gate, out);
}